// round 12
// baseline (speedup 1.0000x reference)
#include <cuda_runtime.h>
#include <cuda_bf16.h>
#include <stdint.h>

#define NN    50000
#define NEDGE 1600000
#define NDIM  1024
#define HID   128
#define CAP   128
#define NBLK64 782   // ceil(NN/64)

// ================= scratch =================
__device__ uint8_t d_pwT[16][2][16384];          // proj_w  [ch][hl][tile]
__device__ uint8_t d_wT [2][2][2][16384];        // [w L/R][hl][ch][tile]
__device__ __nv_bfloat16 d_hLb[(size_t)NN * HID];
__device__ __nv_bfloat16 d_hRb[(size_t)NN * HID];
__device__ int           d_cnt[NN];
__device__ int           d_slot[(size_t)NN * CAP];
__device__ float         d_pool[HID];

// ================= helpers =================
__device__ __forceinline__ uint32_t smem_u32(const void* p) {
    uint32_t a;
    asm("{ .reg .u64 t; cvta.to.shared.u64 t, %1; cvt.u32.u64 %0, t; }" : "=r"(a) : "l"(p));
    return a;
}
#define SWZ128(o) ((o) ^ (((o) >> 3) & 0x70))

__device__ __forceinline__ uint32_t packbf2(__nv_bfloat16 a, __nv_bfloat16 b) {
    return (uint32_t)__bfloat16_as_ushort(a) | ((uint32_t)__bfloat16_as_ushort(b) << 16);
}
__device__ __forceinline__ void split4(float4 v, uint2& hi, uint2& lo) {
    __nv_bfloat16 hx = __float2bfloat16(v.x), hy = __float2bfloat16(v.y);
    __nv_bfloat16 hz = __float2bfloat16(v.z), hw = __float2bfloat16(v.w);
    __nv_bfloat16 lx = __float2bfloat16(v.x - __bfloat162float(hx));
    __nv_bfloat16 ly = __float2bfloat16(v.y - __bfloat162float(hy));
    __nv_bfloat16 lz = __float2bfloat16(v.z - __bfloat162float(hz));
    __nv_bfloat16 lw = __float2bfloat16(v.w - __bfloat162float(hw));
    hi.x = packbf2(hx, hy); hi.y = packbf2(hz, hw);
    lo.x = packbf2(lx, ly); lo.y = packbf2(lz, lw);
}
__device__ __forceinline__ uint2 cvt4hi(float4 v) {
    uint2 hi;
    hi.x = packbf2(__float2bfloat16(v.x), __float2bfloat16(v.y));
    hi.y = packbf2(__float2bfloat16(v.z), __float2bfloat16(v.w));
    return hi;
}

#define LDSM_X4(r, a) \
    asm volatile("ldmatrix.sync.aligned.m8n8.x4.shared.b16 {%0,%1,%2,%3}, [%4];" \
        : "=r"((r)[0]), "=r"((r)[1]), "=r"((r)[2]), "=r"((r)[3]) : "r"(a))
#define LDSM_X2(r, a) \
    asm volatile("ldmatrix.sync.aligned.m8n8.x2.shared.b16 {%0,%1}, [%2];" \
        : "=r"((r)[0]), "=r"((r)[1]) : "r"(a))
#define MMA_BF16(d, a, b) \
    asm volatile("mma.sync.aligned.m16n8k16.row.col.f32.bf16.bf16.f32 " \
        "{%0,%1,%2,%3}, {%4,%5,%6,%7}, {%8,%9}, {%0,%1,%2,%3};" \
        : "+f"((d)[0]), "+f"((d)[1]), "+f"((d)[2]), "+f"((d)[3]) \
        : "r"((a)[0]), "r"((a)[1]), "r"((a)[2]), "r"((a)[3]), "r"((b)[0]), "r"((b)[1]))

#define CP_A16(dst, src) \
    asm volatile("cp.async.cg.shared.global [%0], [%1], 16;" :: "r"(dst), "l"(src))
#define CP_COMMIT() asm volatile("cp.async.commit_group;")
#define CP_WAIT0()  asm volatile("cp.async.wait_group 0;" ::: "memory")
#define CP_WAIT1()  asm volatile("cp.async.wait_group 1;" ::: "memory")

__device__ __forceinline__ uint32_t addrA(uint32_t base, int MI, int ks, int lane) {
    int row  = MI * 16 + (lane & 15);
    int kb   = ks * 32 + ((lane >> 4) << 4);
    return base + SWZ128((uint32_t)(row * 128 + kb));
}
__device__ __forceinline__ uint32_t addrB(uint32_t base, int NI, int ks, int lane) {
    int row = NI * 8 + (lane & 7);
    int kb  = ks * 32 + (((lane >> 3) & 1) << 4);
    return base + SWZ128((uint32_t)(row * 128 + kb));
}

// ================= K0 =================
__global__ void zero_kernel() {
    int i = blockIdx.x * blockDim.x + threadIdx.x;
    if (i < NN)  d_cnt[i] = 0;
    if (i < HID) d_pool[i] = 0.f;
}

// ================= Kp: pre-split weights =================
__global__ void presplit_kernel(const float* __restrict__ pw,
                                const float* __restrict__ wl,
                                const float* __restrict__ wr)
{
    int i = blockIdx.x * blockDim.x + threadIdx.x;
    if (i < 32768) {
        int n  = i >> 8;
        int k4 = (i & 255) << 2;
        int ch = k4 >> 6, kk = k4 & 63;
        float4 v = ((const float4*)pw)[i];
        uint2 hi, lo; split4(v, hi, lo);
        uint32_t sw = SWZ128((uint32_t)(n * 128 + kk * 2));
        *(uint2*)&d_pwT[ch][0][sw] = hi;
        *(uint2*)&d_pwT[ch][1][sw] = lo;
    } else if (i < 40960) {
        int j = i - 32768;
        int w = j >= 4096;
        if (w) j -= 4096;
        const float* W = w ? wr : wl;
        int n  = j >> 5;
        int k4 = (j & 31) << 2;
        int ch = k4 >> 6, kk = k4 & 63;
        float4 v = ((const float4*)W)[j];
        uint2 hi, lo; split4(v, hi, lo);
        uint32_t sw = SWZ128((uint32_t)(n * 128 + kk * 2));
        *(uint2*)&d_wT[w][0][ch][sw] = hi;
        *(uint2*)&d_wT[w][1][ch][sw] = lo;
    }
}

// ================= KF: fused, M=64 tiles, 2 CTAs/SM =================
// smem (96KB):
//   A stage s (x hi) @ s*8192
//   Wproj stage s @ 16384 + s*32768
//   post-mainloop: h hi ch @ ch*8192; h lo ch @ 16384 + ch*8192; WL/WR @ 32768
#define KF_SMEM 98304

__global__ __launch_bounds__(256, 2)
void fused_mma_kernel(const float* __restrict__ X, const float* __restrict__ bias,
                      const float* __restrict__ bL)
{
    extern __shared__ char smem[];
    const uint32_t sb = smem_u32(smem);
    const int tid  = threadIdx.x;
    const int lane = tid & 31;
    const int wid  = tid >> 5;
    const int wm   = wid & 1;
    const int wn   = wid >> 1;
    const int row0 = blockIdx.x * 64;

    float acc[2][4][4];
    #pragma unroll
    for (int i = 0; i < 2; i++)
        #pragma unroll
        for (int j = 0; j < 4; j++)
            #pragma unroll
            for (int q = 0; q < 4; q++) acc[i][j][q] = 0.f;

    // ---- prologue
    float4 xv[4];
    #pragma unroll
    for (int it = 0; it < 4; it++) {
        int e = tid + it * 256;
        int r = e >> 4, c4 = (e & 15) << 2;
        int gm = row0 + r;
        xv[it] = (gm < NN) ? *(const float4*)&X[(size_t)gm * NDIM + c4]
                           : make_float4(0.f, 0.f, 0.f, 0.f);
    }
    {
        uint32_t wst = sb + 16384;
        const uint8_t* src = &d_pwT[0][0][0];
        #pragma unroll
        for (int q = 0; q < 8; q++)
            CP_A16(wst + tid * 16 + q * 4096, src + tid * 16 + q * 4096);
        CP_COMMIT();
    }
    #pragma unroll
    for (int it = 0; it < 4; it++) {
        int e = tid + it * 256;
        int r = e >> 4, c4 = (e & 15) << 2;
        *(uint2*)(smem + SWZ128((uint32_t)(r * 128 + c4 * 2))) = cvt4hi(xv[it]);
    }

    // ---- mainloop
    #pragma unroll 1
    for (int c = 0; c < 16; c++) {
        const int s = c & 1;
        if (c < 15) {
            uint32_t wst = sb + 16384 + (s ^ 1) * 32768;
            const uint8_t* src = &d_pwT[c + 1][0][0];
            #pragma unroll
            for (int q = 0; q < 8; q++)
                CP_A16(wst + tid * 16 + q * 4096, src + tid * 16 + q * 4096);
            CP_COMMIT();
            CP_WAIT1();
        } else {
            CP_WAIT0();
        }
        __syncthreads();

        if (c < 15) {
            const int kc = (c + 1) * 64;
            #pragma unroll
            for (int it = 0; it < 4; it++) {
                int e = tid + it * 256;
                int r = e >> 4, c4 = (e & 15) << 2;
                int gm = row0 + r;
                xv[it] = (gm < NN) ? *(const float4*)&X[(size_t)gm * NDIM + kc + c4]
                                   : make_float4(0.f, 0.f, 0.f, 0.f);
            }
        }

        const uint32_t aHi = sb + s * 8192;
        const uint32_t bHi = sb + 16384 + s * 32768, bLo = bHi + 16384;
        #pragma unroll
        for (int ks = 0; ks < 4; ks++) {
            uint32_t ahi[2][4];
            #pragma unroll
            for (int mi = 0; mi < 2; mi++)
                LDSM_X4(ahi[mi], addrA(aHi, wm * 2 + mi, ks, lane));
            #pragma unroll
            for (int ni = 0; ni < 4; ni++) {
                uint32_t bh[2], bl[2];
                LDSM_X2(bh, addrB(bHi, wn * 4 + ni, ks, lane));
                LDSM_X2(bl, addrB(bLo, wn * 4 + ni, ks, lane));
                #pragma unroll
                for (int mi = 0; mi < 2; mi++) {
                    MMA_BF16(acc[mi][ni], ahi[mi], bh);
                    MMA_BF16(acc[mi][ni], ahi[mi], bl);
                }
            }
        }

        if (c < 15) {
            char* base = smem + (s ^ 1) * 8192;
            #pragma unroll
            for (int it = 0; it < 4; it++) {
                int e = tid + it * 256;
                int r = e >> 4, c4 = (e & 15) << 2;
                *(uint2*)(base + SWZ128((uint32_t)(r * 128 + c4 * 2))) = cvt4hi(xv[it]);
            }
        }
        __syncthreads();
    }

    // ---- issue WL cp.async (overlaps h-epilogue ALU)
    {
        const uint8_t* src = &d_wT[0][0][0][0];
        #pragma unroll
        for (int q = 0; q < 16; q++)
            CP_A16(sb + 32768 + tid * 16 + q * 4096, src + tid * 16 + q * 4096);
        CP_COMMIT();
    }

    // ---- h epilogue: bias+relu+split; hi -> ch*8192; lo -> 16384 + ch*8192
    #pragma unroll
    for (int ni = 0; ni < 4; ni++) {
        int cc = wn * 32 + ni * 8 + (lane & 3) * 2;
        int ch = cc >> 6, kk = cc & 63;
        float b0 = bias[cc], b1 = bias[cc + 1];
        #pragma unroll
        for (int mi = 0; mi < 2; mi++) {
            int rl0 = wm * 32 + mi * 16 + (lane >> 2);
            #pragma unroll
            for (int half = 0; half < 2; half++) {
                int rl = rl0 + half * 8;
                float v0 = fmaxf(acc[mi][ni][half * 2 + 0] + b0, 0.f);
                float v1 = fmaxf(acc[mi][ni][half * 2 + 1] + b1, 0.f);
                __nv_bfloat16 h0 = __float2bfloat16(v0), h1 = __float2bfloat16(v1);
                __nv_bfloat16 l0 = __float2bfloat16(v0 - __bfloat162float(h0));
                __nv_bfloat16 l1 = __float2bfloat16(v1 - __bfloat162float(h1));
                uint32_t sw = SWZ128((uint32_t)(rl * 128 + kk * 2));
                *(uint32_t*)(smem + ch * 8192 + sw)         = packbf2(h0, h1);
                *(uint32_t*)(smem + 16384 + ch * 8192 + sw) = packbf2(l0, l1);
            }
        }
    }
    CP_WAIT0();
    __syncthreads();

    // ---- pass 0: hL = h @ WL^T (bf16 out), 3-term
    const uint32_t wlr = sb + 32768;
    float ac2[2][4][4];
    #pragma unroll
    for (int i = 0; i < 2; i++)
        #pragma unroll
        for (int j = 0; j < 4; j++)
            #pragma unroll
            for (int q = 0; q < 4; q++) ac2[i][j][q] = 0.f;

    #pragma unroll
    for (int ks8 = 0; ks8 < 8; ks8++) {
        const int ch = ks8 >> 2, ks = ks8 & 3;
        const uint32_t aHi = sb + ch * 8192, aLo = sb + 16384 + ch * 8192;
        const uint32_t wHi = wlr + ch * 16384, wLo = wlr + 32768 + ch * 16384;
        uint32_t ahi[2][4], alo[2][4];
        #pragma unroll
        for (int mi = 0; mi < 2; mi++) {
            LDSM_X4(ahi[mi], addrA(aHi, wm * 2 + mi, ks, lane));
            LDSM_X4(alo[mi], addrA(aLo, wm * 2 + mi, ks, lane));
        }
        #pragma unroll
        for (int ni = 0; ni < 4; ni++) {
            uint32_t bh[2], bl[2];
            LDSM_X2(bh, addrB(wHi, wn * 4 + ni, ks, lane));
            LDSM_X2(bl, addrB(wLo, wn * 4 + ni, ks, lane));
            #pragma unroll
            for (int mi = 0; mi < 2; mi++) {
                MMA_BF16(ac2[mi][ni], ahi[mi], bh);
                MMA_BF16(ac2[mi][ni], ahi[mi], bl);
                MMA_BF16(ac2[mi][ni], alo[mi], bh);
            }
        }
    }
    __syncthreads();   // WL reads closed

    {
        const uint8_t* src = &d_wT[1][0][0][0];
        #pragma unroll
        for (int q = 0; q < 16; q++)
            CP_A16(wlr + tid * 16 + q * 4096, src + tid * 16 + q * 4096);
        CP_COMMIT();
    }
    #pragma unroll
    for (int ni = 0; ni < 4; ni++) {
        int cc = wn * 32 + ni * 8 + (lane & 3) * 2;
        #pragma unroll
        for (int mi = 0; mi < 2; mi++) {
            int r0 = row0 + wm * 32 + mi * 16 + (lane >> 2);
            #pragma unroll
            for (int half = 0; half < 2; half++) {
                int r = r0 + half * 8;
                if (r < NN) {
                    *(uint32_t*)&d_hLb[(size_t)r * HID + cc] =
                        packbf2(__float2bfloat16(ac2[mi][ni][half * 2 + 0]),
                                __float2bfloat16(ac2[mi][ni][half * 2 + 1]));
                }
            }
        }
    }
    CP_WAIT0();
    __syncthreads();

    // ---- pass 1: hR = h @ WR^T + bL (bf16 out), 3-term
    #pragma unroll
    for (int i = 0; i < 2; i++)
        #pragma unroll
        for (int j = 0; j < 4; j++)
            #pragma unroll
            for (int q = 0; q < 4; q++) ac2[i][j][q] = 0.f;

    #pragma unroll
    for (int ks8 = 0; ks8 < 8; ks8++) {
        const int ch = ks8 >> 2, ks = ks8 & 3;
        const uint32_t aHi = sb + ch * 8192, aLo = sb + 16384 + ch * 8192;
        const uint32_t wHi = wlr + ch * 16384, wLo = wlr + 32768 + ch * 16384;
        uint32_t ahi[2][4], alo[2][4];
        #pragma unroll
        for (int mi = 0; mi < 2; mi++) {
            LDSM_X4(ahi[mi], addrA(aHi, wm * 2 + mi, ks, lane));
            LDSM_X4(alo[mi], addrA(aLo, wm * 2 + mi, ks, lane));
        }
        #pragma unroll
        for (int ni = 0; ni < 4; ni++) {
            uint32_t bh[2], bl[2];
            LDSM_X2(bh, addrB(wHi, wn * 4 + ni, ks, lane));
            LDSM_X2(bl, addrB(wLo, wn * 4 + ni, ks, lane));
            #pragma unroll
            for (int mi = 0; mi < 2; mi++) {
                MMA_BF16(ac2[mi][ni], ahi[mi], bh);
                MMA_BF16(ac2[mi][ni], ahi[mi], bl);
                MMA_BF16(ac2[mi][ni], alo[mi], bh);
            }
        }
    }
    #pragma unroll
    for (int ni = 0; ni < 4; ni++) {
        int cc = wn * 32 + ni * 8 + (lane & 3) * 2;
        float b0 = bL[cc], b1 = bL[cc + 1];
        #pragma unroll
        for (int mi = 0; mi < 2; mi++) {
            int r0 = row0 + wm * 32 + mi * 16 + (lane >> 2);
            #pragma unroll
            for (int half = 0; half < 2; half++) {
                int r = r0 + half * 8;
                if (r < NN) {
                    *(uint32_t*)&d_hRb[(size_t)r * HID + cc] =
                        packbf2(__float2bfloat16(ac2[mi][ni][half * 2 + 0] + b0),
                                __float2bfloat16(ac2[mi][ni][half * 2 + 1] + b1));
                }
            }
        }
    }
}

// ================= K3: bucket edges by dst =================
__global__ void edge_bucket_kernel(const int* __restrict__ ei) {
    int i = blockIdx.x * blockDim.x + threadIdx.x;
    if (i >= NEDGE) return;
    int src = ei[i];
    int dst = ei[NEDGE + i];
    if ((unsigned)src >= NN || (unsigned)dst >= NN) return;
    int pos = atomicAdd(&d_cnt[dst], 1);
    if (pos < CAP) d_slot[(size_t)dst * CAP + pos] = src;
}

// ================= K4: gather + combine + LN + relu + pool (MLP-8) =================
__global__ __launch_bounds__(256)
void gather_ln_pool_kernel(const float* __restrict__ lng,
                           const float* __restrict__ lnb)
{
    const int lane   = threadIdx.x & 31;
    const int warp   = threadIdx.x >> 5;
    const int nwarps = blockDim.x >> 5;

    const float4  g4  = ((const float4*)lng)[lane];
    const float4  b4  = ((const float4*)lnb)[lane];

    float4 pacc = make_float4(0.f, 0.f, 0.f, 0.f);

    for (int node = blockIdx.x * nwarps + warp; node < NN;
         node += gridDim.x * nwarps)
    {
        int deg = d_cnt[node];
        int dn  = min(deg, CAP);

        int sl[4];
        #pragma unroll
        for (int q = 0; q < 4; q++) {
            int idx = q * 32 + lane;
            sl[q] = (idx < dn) ? d_slot[(size_t)node * CAP + idx] : 0;
        }

        float4 a0 = make_float4(0.f, 0.f, 0.f, 0.f);
        float4 a1 = make_float4(0.f, 0.f, 0.f, 0.f);
        float4 a2 = make_float4(0.f, 0.f, 0.f, 0.f);
        float4 a3 = make_float4(0.f, 0.f, 0.f, 0.f);

        #pragma unroll
        for (int q = 0; q < 4; q++) {
            int base = q * 32;
            if (base >= dn) break;
            int cnt = min(32, dn - base);
            int my  = sl[q];
            int j = 0;
            #pragma unroll 1
            for (; j + 8 <= cnt; j += 8) {
                int s0 = __shfl_sync(0xffffffffu, my, j + 0);
                int s1 = __shfl_sync(0xffffffffu, my, j + 1);
                int s2 = __shfl_sync(0xffffffffu, my, j + 2);
                int s3 = __shfl_sync(0xffffffffu, my, j + 3);
                int s4 = __shfl_sync(0xffffffffu, my, j + 4);
                int s5 = __shfl_sync(0xffffffffu, my, j + 5);
                int s6 = __shfl_sync(0xffffffffu, my, j + 6);
                int s7 = __shfl_sync(0xffffffffu, my, j + 7);
                uint2 p0 = *(const uint2*)&d_hLb[(size_t)s0 * HID + lane * 4];
                uint2 p1 = *(const uint2*)&d_hLb[(size_t)s1 * HID + lane * 4];
                uint2 p2 = *(const uint2*)&d_hLb[(size_t)s2 * HID + lane * 4];
                uint2 p3 = *(const uint2*)&d_hLb[(size_t)s3 * HID + lane * 4];
                uint2 p4 = *(const uint2*)&d_hLb[(size_t)s4 * HID + lane * 4];
                uint2 p5 = *(const uint2*)&d_hLb[(size_t)s5 * HID + lane * 4];
                uint2 p6 = *(const uint2*)&d_hLb[(size_t)s6 * HID + lane * 4];
                uint2 p7 = *(const uint2*)&d_hLb[(size_t)s7 * HID + lane * 4];
                float2 f;
                f = __bfloat1622float2(*(__nv_bfloat162*)&p0.x); a0.x += f.x; a0.y += f.y;
                f = __bfloat1622float2(*(__nv_bfloat162*)&p0.y); a0.z += f.x; a0.w += f.y;
                f = __bfloat1622float2(*(__nv_bfloat162*)&p1.x); a1.x += f.x; a1.y += f.y;
                f = __bfloat1622float2(*(__nv_bfloat162*)&p1.y); a1.z += f.x; a1.w += f.y;
                f = __bfloat1622float2(*(__nv_bfloat162*)&p2.x); a2.x += f.x; a2.y += f.y;
                f = __bfloat1622float2(*(__nv_bfloat162*)&p2.y); a2.z += f.x; a2.w += f.y;
                f = __bfloat1622float2(*(__nv_bfloat162*)&p3.x); a3.x += f.x; a3.y += f.y;
                f = __bfloat1622float2(*(__nv_bfloat162*)&p3.y); a3.z += f.x; a3.w += f.y;
                f = __bfloat1622float2(*(__nv_bfloat162*)&p4.x); a0.x += f.x; a0.y += f.y;
                f = __bfloat1622float2(*(__nv_bfloat162*)&p4.y); a0.z += f.x; a0.w += f.y;
                f = __bfloat1622float2(*(__nv_bfloat162*)&p5.x); a1.x += f.x; a1.y += f.y;
                f = __bfloat1622float2(*(__nv_bfloat162*)&p5.y); a1.z += f.x; a1.w += f.y;
                f = __bfloat1622float2(*(__nv_bfloat162*)&p6.x); a2.x += f.x; a2.y += f.y;
                f = __bfloat1622float2(*(__nv_bfloat162*)&p6.y); a2.z += f.x; a2.w += f.y;
                f = __bfloat1622float2(*(__nv_bfloat162*)&p7.x); a3.x += f.x; a3.y += f.y;
                f = __bfloat1622float2(*(__nv_bfloat162*)&p7.y); a3.z += f.x; a3.w += f.y;
            }
            for (; j < cnt; j++) {
                int s = __shfl_sync(0xffffffffu, my, j);
                uint2 p = *(const uint2*)&d_hLb[(size_t)s * HID + lane * 4];
                float2 f;
                f = __bfloat1622float2(*(__nv_bfloat162*)&p.x); a0.x += f.x; a0.y += f.y;
                f = __bfloat1622float2(*(__nv_bfloat162*)&p.y); a0.z += f.x; a0.w += f.y;
            }
        }
        float4 acc;
        acc.x = (a0.x + a1.x) + (a2.x + a3.x);
        acc.y = (a0.y + a1.y) + (a2.y + a3.y);
        acc.z = (a0.z + a1.z) + (a2.z + a3.z);
        acc.w = (a0.w + a1.w) + (a2.w + a3.w);

        float inv = 1.f / fmaxf((float)deg, 1.f);
        uint2 pr = *(const uint2*)&d_hRb[(size_t)node * HID + lane * 4];
        float2 h0 = __bfloat1622float2(*(__nv_bfloat162*)&pr.x);
        float2 h1 = __bfloat1622float2(*(__nv_bfloat162*)&pr.y);
        float4 y;
        y.x = fmaf(acc.x, inv, h0.x);
        y.y = fmaf(acc.y, inv, h0.y);
        y.z = fmaf(acc.z, inv, h1.x);
        y.w = fmaf(acc.w, inv, h1.y);

        float s1 = y.x + y.y + y.z + y.w;
        float s2 = y.x * y.x + y.y * y.y + y.z * y.z + y.w * y.w;
        #pragma unroll
        for (int o = 16; o > 0; o >>= 1) {
            s1 += __shfl_xor_sync(0xffffffffu, s1, o);
            s2 += __shfl_xor_sync(0xffffffffu, s2, o);
        }
        float mu   = s1 * (1.f / 128.f);
        float var  = s2 * (1.f / 128.f) - mu * mu;
        float rstd = rsqrtf(var + 1e-5f);

        pacc.x += fmaxf((y.x - mu) * rstd * g4.x + b4.x, 0.f);
        pacc.y += fmaxf((y.y - mu) * rstd * g4.y + b4.y, 0.f);
        pacc.z += fmaxf((y.z - mu) * rstd * g4.z + b4.z, 0.f);
        pacc.w += fmaxf((y.w - mu) * rstd * g4.w + b4.w, 0.f);
    }

    __shared__ float sp[8][128];
    ((float4*)sp[warp])[lane] = pacc;
    __syncthreads();
    int t = threadIdx.x;
    if (t < HID) {
        float s = 0.f;
        #pragma unroll
        for (int w = 0; w < 8; w++) s += sp[w][t];
        atomicAdd(&d_pool[t], s);
    }
}

// ================= K5: final linear =================
__global__ void final_kernel(const float* __restrict__ ow,
                             const float* __restrict__ ob,
                             float* __restrict__ out)
{
    __shared__ float g[128];
    int t = threadIdx.x;
    g[t] = d_pool[t] * (1.f / (float)NN);
    __syncthreads();
    float s = ob[t];
    #pragma unroll 8
    for (int f = 0; f < 128; f++)
        s = fmaf(g[f], ow[(size_t)t * 128 + f], s);
    out[t] = s;
}

// ================= launch =================
extern "C" void kernel_launch(void* const* d_in, const int* in_sizes, int n_in,
                              void* d_out, int out_size)
{
    const float* x       = (const float*)d_in[0];
    const int*   ei      = (const int*)d_in[1];
    const float* proj_w  = (const float*)d_in[2];
    const float* proj_b  = (const float*)d_in[3];
    const float* lin_l_w = (const float*)d_in[4];
    const float* lin_l_b = (const float*)d_in[5];
    const float* lin_r_w = (const float*)d_in[6];
    const float* ln_g    = (const float*)d_in[7];
    const float* ln_b    = (const float*)d_in[8];
    const float* out_w   = (const float*)d_in[9];
    const float* out_b   = (const float*)d_in[10];
    float* out = (float*)d_out;

    static bool init_done = false;
    static cudaStream_t s2;
    static cudaEvent_t evA, evB;
    if (!init_done) {
        cudaFuncSetAttribute(fused_mma_kernel, cudaFuncAttributeMaxDynamicSharedMemorySize, KF_SMEM);
        cudaStreamCreateWithFlags(&s2, cudaStreamNonBlocking);
        cudaEventCreateWithFlags(&evA, cudaEventDisableTiming);
        cudaEventCreateWithFlags(&evB, cudaEventDisableTiming);
        init_done = true;
    }

    // fork: branch B = zero -> bucket (independent of GEMM chain)
    cudaEventRecord(evA, 0);
    cudaStreamWaitEvent(s2, evA, 0);
    zero_kernel<<<(NN + 255) / 256, 256, 0, s2>>>();
    edge_bucket_kernel<<<(NEDGE + 255) / 256, 256, 0, s2>>>(ei);
    cudaEventRecord(evB, s2);

    // branch A (main stream): presplit -> fused
    presplit_kernel<<<160, 256>>>(proj_w, lin_l_w, lin_r_w);
    fused_mma_kernel<<<NBLK64, 256, KF_SMEM>>>(x, proj_b, lin_l_b);

    // join, then gather -> final
    cudaStreamWaitEvent(0, evB, 0);
    gather_ln_pool_kernel<<<1184, 256>>>(ln_g, ln_b);
    final_kernel<<<1, 128>>>(out_w, out_b, out);
}

// round 13
// speedup vs baseline: 1.0092x; 1.0092x over previous
#include <cuda_runtime.h>
#include <cuda_bf16.h>
#include <stdint.h>

#define NN    50000
#define NEDGE 1600000
#define NDIM  1024
#define HID   128
#define CAP   128
#define NBLK64 782   // ceil(NN/64)

// ================= scratch =================
__device__ uint8_t d_pwT[16][2][16384];          // proj_w  [ch][hl][tile]
__device__ uint8_t d_wT [2][2][2][16384];        // [w L/R][hl][ch][tile]
__device__ __nv_bfloat16 d_hLb[(size_t)NN * HID];
__device__ __nv_bfloat16 d_hRb[(size_t)NN * HID];
__device__ int           d_cnt[NN];
__device__ int           d_slot[(size_t)NN * CAP];
__device__ float         d_pool[HID];

// ================= helpers =================
__device__ __forceinline__ uint32_t smem_u32(const void* p) {
    uint32_t a;
    asm("{ .reg .u64 t; cvta.to.shared.u64 t, %1; cvt.u32.u64 %0, t; }" : "=r"(a) : "l"(p));
    return a;
}
#define SWZ128(o) ((o) ^ (((o) >> 3) & 0x70))

__device__ __forceinline__ uint32_t packbf2(__nv_bfloat16 a, __nv_bfloat16 b) {
    return (uint32_t)__bfloat16_as_ushort(a) | ((uint32_t)__bfloat16_as_ushort(b) << 16);
}
__device__ __forceinline__ void split4(float4 v, uint2& hi, uint2& lo) {
    __nv_bfloat16 hx = __float2bfloat16(v.x), hy = __float2bfloat16(v.y);
    __nv_bfloat16 hz = __float2bfloat16(v.z), hw = __float2bfloat16(v.w);
    __nv_bfloat16 lx = __float2bfloat16(v.x - __bfloat162float(hx));
    __nv_bfloat16 ly = __float2bfloat16(v.y - __bfloat162float(hy));
    __nv_bfloat16 lz = __float2bfloat16(v.z - __bfloat162float(hz));
    __nv_bfloat16 lw = __float2bfloat16(v.w - __bfloat162float(hw));
    hi.x = packbf2(hx, hy); hi.y = packbf2(hz, hw);
    lo.x = packbf2(lx, ly); lo.y = packbf2(lz, lw);
}
__device__ __forceinline__ uint2 cvt4hi(float4 v) {
    uint2 hi;
    hi.x = packbf2(__float2bfloat16(v.x), __float2bfloat16(v.y));
    hi.y = packbf2(__float2bfloat16(v.z), __float2bfloat16(v.w));
    return hi;
}

#define LDSM_X4(r, a) \
    asm volatile("ldmatrix.sync.aligned.m8n8.x4.shared.b16 {%0,%1,%2,%3}, [%4];" \
        : "=r"((r)[0]), "=r"((r)[1]), "=r"((r)[2]), "=r"((r)[3]) : "r"(a))
#define MMA_BF16(d, a, b0, b1) \
    asm volatile("mma.sync.aligned.m16n8k16.row.col.f32.bf16.bf16.f32 " \
        "{%0,%1,%2,%3}, {%4,%5,%6,%7}, {%8,%9}, {%0,%1,%2,%3};" \
        : "+f"((d)[0]), "+f"((d)[1]), "+f"((d)[2]), "+f"((d)[3]) \
        : "r"((a)[0]), "r"((a)[1]), "r"((a)[2]), "r"((a)[3]), "r"(b0), "r"(b1))

#define CP_A16(dst, src) \
    asm volatile("cp.async.cg.shared.global [%0], [%1], 16;" :: "r"(dst), "l"(src))
#define CP_COMMIT() asm volatile("cp.async.commit_group;")
#define CP_WAIT0()  asm volatile("cp.async.wait_group 0;" ::: "memory")
#define CP_WAIT1()  asm volatile("cp.async.wait_group 1;" ::: "memory")

__device__ __forceinline__ uint32_t addrA(uint32_t base, int MI, int ks, int lane) {
    int row  = MI * 16 + (lane & 15);
    int kb   = ks * 32 + ((lane >> 4) << 4);
    return base + SWZ128((uint32_t)(row * 128 + kb));
}
// B x4: loads fragments for TWO adjacent n-tiles (pair p -> ni = 2p, 2p+1).
// lanes 0-7: ni=2p rows @ klo; 8-15: ni=2p rows @ khi; 16-23: ni=2p+1 @ klo; 24-31: @ khi
__device__ __forceinline__ uint32_t addrB4(uint32_t base, int p, int ks, int lane) {
    int ni  = p * 2 + ((lane >> 4) & 1);
    int row = ni * 8 + (lane & 7);
    int kb  = ks * 32 + (((lane >> 3) & 1) << 4);
    return base + SWZ128((uint32_t)(row * 128 + kb));
}

// ================= K0 =================
__global__ void zero_kernel() {
    int i = blockIdx.x * blockDim.x + threadIdx.x;
    if (i < NN)  d_cnt[i] = 0;
    if (i < HID) d_pool[i] = 0.f;
}

// ================= Kp: pre-split weights =================
__global__ void presplit_kernel(const float* __restrict__ pw,
                                const float* __restrict__ wl,
                                const float* __restrict__ wr)
{
    int i = blockIdx.x * blockDim.x + threadIdx.x;
    if (i < 32768) {
        int n  = i >> 8;
        int k4 = (i & 255) << 2;
        int ch = k4 >> 6, kk = k4 & 63;
        float4 v = ((const float4*)pw)[i];
        uint2 hi, lo; split4(v, hi, lo);
        uint32_t sw = SWZ128((uint32_t)(n * 128 + kk * 2));
        *(uint2*)&d_pwT[ch][0][sw] = hi;
        *(uint2*)&d_pwT[ch][1][sw] = lo;
    } else if (i < 40960) {
        int j = i - 32768;
        int w = j >= 4096;
        if (w) j -= 4096;
        const float* W = w ? wr : wl;
        int n  = j >> 5;
        int k4 = (j & 31) << 2;
        int ch = k4 >> 6, kk = k4 & 63;
        float4 v = ((const float4*)W)[j];
        uint2 hi, lo; split4(v, hi, lo);
        uint32_t sw = SWZ128((uint32_t)(n * 128 + kk * 2));
        *(uint2*)&d_wT[w][0][ch][sw] = hi;
        *(uint2*)&d_wT[w][1][ch][sw] = lo;
    }
}

// ================= KF: fused, M=64 tiles, 2 CTAs/SM =================
// smem (96KB): A stage s @ s*8192; Wproj stage s @ 16384 + s*32768
//   post-mainloop: h hi ch @ ch*8192; h lo ch @ 16384 + ch*8192; WL/WR @ 32768
#define KF_SMEM 98304

__global__ __launch_bounds__(256, 2)
void fused_mma_kernel(const float* __restrict__ X, const float* __restrict__ bias,
                      const float* __restrict__ bL)
{
    extern __shared__ char smem[];
    const uint32_t sb = smem_u32(smem);
    const int tid  = threadIdx.x;
    const int lane = tid & 31;
    const int wid  = tid >> 5;
    const int wm   = wid & 1;
    const int wn   = wid >> 1;
    const int row0 = blockIdx.x * 64;

    float acc[2][4][4];
    #pragma unroll
    for (int i = 0; i < 2; i++)
        #pragma unroll
        for (int j = 0; j < 4; j++)
            #pragma unroll
            for (int q = 0; q < 4; q++) acc[i][j][q] = 0.f;

    // ---- prologue
    float4 xv[4];
    #pragma unroll
    for (int it = 0; it < 4; it++) {
        int e = tid + it * 256;
        int r = e >> 4, c4 = (e & 15) << 2;
        int gm = row0 + r;
        xv[it] = (gm < NN) ? *(const float4*)&X[(size_t)gm * NDIM + c4]
                           : make_float4(0.f, 0.f, 0.f, 0.f);
    }
    {
        uint32_t wst = sb + 16384;
        const uint8_t* src = &d_pwT[0][0][0];
        #pragma unroll
        for (int q = 0; q < 8; q++)
            CP_A16(wst + tid * 16 + q * 4096, src + tid * 16 + q * 4096);
        CP_COMMIT();
    }
    #pragma unroll
    for (int it = 0; it < 4; it++) {
        int e = tid + it * 256;
        int r = e >> 4, c4 = (e & 15) << 2;
        *(uint2*)(smem + SWZ128((uint32_t)(r * 128 + c4 * 2))) = cvt4hi(xv[it]);
    }

    // ---- mainloop
    #pragma unroll 1
    for (int c = 0; c < 16; c++) {
        const int s = c & 1;
        if (c < 15) {
            uint32_t wst = sb + 16384 + (s ^ 1) * 32768;
            const uint8_t* src = &d_pwT[c + 1][0][0];
            #pragma unroll
            for (int q = 0; q < 8; q++)
                CP_A16(wst + tid * 16 + q * 4096, src + tid * 16 + q * 4096);
            CP_COMMIT();
            CP_WAIT1();
        } else {
            CP_WAIT0();
        }
        __syncthreads();

        if (c < 15) {
            const int kc = (c + 1) * 64;
            #pragma unroll
            for (int it = 0; it < 4; it++) {
                int e = tid + it * 256;
                int r = e >> 4, c4 = (e & 15) << 2;
                int gm = row0 + r;
                xv[it] = (gm < NN) ? *(const float4*)&X[(size_t)gm * NDIM + kc + c4]
                                   : make_float4(0.f, 0.f, 0.f, 0.f);
            }
        }

        const uint32_t aHi = sb + s * 8192;
        const uint32_t bHi = sb + 16384 + s * 32768, bLo = bHi + 16384;
        #pragma unroll
        for (int ks = 0; ks < 4; ks++) {
            uint32_t ahi[2][4];
            #pragma unroll
            for (int mi = 0; mi < 2; mi++)
                LDSM_X4(ahi[mi], addrA(aHi, wm * 2 + mi, ks, lane));
            uint32_t bh[2][4], bl[2][4];
            #pragma unroll
            for (int p = 0; p < 2; p++) {
                LDSM_X4(bh[p], addrB4(bHi, wn * 2 + p, ks, lane));
                LDSM_X4(bl[p], addrB4(bLo, wn * 2 + p, ks, lane));
            }
            // wave 1: ahi x bh (8 independent accs)
            #pragma unroll
            for (int ni = 0; ni < 4; ni++)
                #pragma unroll
                for (int mi = 0; mi < 2; mi++)
                    MMA_BF16(acc[mi][ni], ahi[mi], bh[ni >> 1][(ni & 1) * 2], bh[ni >> 1][(ni & 1) * 2 + 1]);
            // wave 2: ahi x bl
            #pragma unroll
            for (int ni = 0; ni < 4; ni++)
                #pragma unroll
                for (int mi = 0; mi < 2; mi++)
                    MMA_BF16(acc[mi][ni], ahi[mi], bl[ni >> 1][(ni & 1) * 2], bl[ni >> 1][(ni & 1) * 2 + 1]);
        }

        if (c < 15) {
            char* base = smem + (s ^ 1) * 8192;
            #pragma unroll
            for (int it = 0; it < 4; it++) {
                int e = tid + it * 256;
                int r = e >> 4, c4 = (e & 15) << 2;
                *(uint2*)(base + SWZ128((uint32_t)(r * 128 + c4 * 2))) = cvt4hi(xv[it]);
            }
        }
        __syncthreads();
    }

    // ---- issue WL cp.async (overlaps h-epilogue ALU)
    {
        const uint8_t* src = &d_wT[0][0][0][0];
        #pragma unroll
        for (int q = 0; q < 16; q++)
            CP_A16(sb + 32768 + tid * 16 + q * 4096, src + tid * 16 + q * 4096);
        CP_COMMIT();
    }

    // ---- h epilogue: bias+relu+split
    #pragma unroll
    for (int ni = 0; ni < 4; ni++) {
        int cc = wn * 32 + ni * 8 + (lane & 3) * 2;
        int ch = cc >> 6, kk = cc & 63;
        float b0 = bias[cc], b1 = bias[cc + 1];
        #pragma unroll
        for (int mi = 0; mi < 2; mi++) {
            int rl0 = wm * 32 + mi * 16 + (lane >> 2);
            #pragma unroll
            for (int half = 0; half < 2; half++) {
                int rl = rl0 + half * 8;
                float v0 = fmaxf(acc[mi][ni][half * 2 + 0] + b0, 0.f);
                float v1 = fmaxf(acc[mi][ni][half * 2 + 1] + b1, 0.f);
                __nv_bfloat16 h0 = __float2bfloat16(v0), h1 = __float2bfloat16(v1);
                __nv_bfloat16 l0 = __float2bfloat16(v0 - __bfloat162float(h0));
                __nv_bfloat16 l1 = __float2bfloat16(v1 - __bfloat162float(h1));
                uint32_t sw = SWZ128((uint32_t)(rl * 128 + kk * 2));
                *(uint32_t*)(smem + ch * 8192 + sw)         = packbf2(h0, h1);
                *(uint32_t*)(smem + 16384 + ch * 8192 + sw) = packbf2(l0, l1);
            }
        }
    }
    CP_WAIT0();
    __syncthreads();

    // ---- pass 0: hL = h @ WL^T (bf16 out), 3-term, wave-ordered
    const uint32_t wlr = sb + 32768;
    float ac2[2][4][4];
    #pragma unroll
    for (int i = 0; i < 2; i++)
        #pragma unroll
        for (int j = 0; j < 4; j++)
            #pragma unroll
            for (int q = 0; q < 4; q++) ac2[i][j][q] = 0.f;

    #pragma unroll
    for (int ks8 = 0; ks8 < 8; ks8++) {
        const int ch = ks8 >> 2, ks = ks8 & 3;
        const uint32_t aHi = sb + ch * 8192, aLo = sb + 16384 + ch * 8192;
        const uint32_t wHi = wlr + ch * 16384, wLo = wlr + 32768 + ch * 16384;
        uint32_t ahi[2][4], alo[2][4];
        #pragma unroll
        for (int mi = 0; mi < 2; mi++) {
            LDSM_X4(ahi[mi], addrA(aHi, wm * 2 + mi, ks, lane));
            LDSM_X4(alo[mi], addrA(aLo, wm * 2 + mi, ks, lane));
        }
        uint32_t bh[2][4], bl[2][4];
        #pragma unroll
        for (int p = 0; p < 2; p++) {
            LDSM_X4(bh[p], addrB4(wHi, wn * 2 + p, ks, lane));
            LDSM_X4(bl[p], addrB4(wLo, wn * 2 + p, ks, lane));
        }
        #pragma unroll
        for (int ni = 0; ni < 4; ni++)
            #pragma unroll
            for (int mi = 0; mi < 2; mi++)
                MMA_BF16(ac2[mi][ni], ahi[mi], bh[ni >> 1][(ni & 1) * 2], bh[ni >> 1][(ni & 1) * 2 + 1]);
        #pragma unroll
        for (int ni = 0; ni < 4; ni++)
            #pragma unroll
            for (int mi = 0; mi < 2; mi++)
                MMA_BF16(ac2[mi][ni], ahi[mi], bl[ni >> 1][(ni & 1) * 2], bl[ni >> 1][(ni & 1) * 2 + 1]);
        #pragma unroll
        for (int ni = 0; ni < 4; ni++)
            #pragma unroll
            for (int mi = 0; mi < 2; mi++)
                MMA_BF16(ac2[mi][ni], alo[mi], bh[ni >> 1][(ni & 1) * 2], bh[ni >> 1][(ni & 1) * 2 + 1]);
    }
    __syncthreads();   // WL reads closed

    {
        const uint8_t* src = &d_wT[1][0][0][0];
        #pragma unroll
        for (int q = 0; q < 16; q++)
            CP_A16(wlr + tid * 16 + q * 4096, src + tid * 16 + q * 4096);
        CP_COMMIT();
    }
    #pragma unroll
    for (int ni = 0; ni < 4; ni++) {
        int cc = wn * 32 + ni * 8 + (lane & 3) * 2;
        #pragma unroll
        for (int mi = 0; mi < 2; mi++) {
            int r0 = row0 + wm * 32 + mi * 16 + (lane >> 2);
            #pragma unroll
            for (int half = 0; half < 2; half++) {
                int r = r0 + half * 8;
                if (r < NN) {
                    *(uint32_t*)&d_hLb[(size_t)r * HID + cc] =
                        packbf2(__float2bfloat16(ac2[mi][ni][half * 2 + 0]),
                                __float2bfloat16(ac2[mi][ni][half * 2 + 1]));
                }
            }
        }
    }
    CP_WAIT0();
    __syncthreads();

    // ---- pass 1: hR = h @ WR^T + bL (bf16 out), 3-term, wave-ordered
    #pragma unroll
    for (int i = 0; i < 2; i++)
        #pragma unroll
        for (int j = 0; j < 4; j++)
            #pragma unroll
            for (int q = 0; q < 4; q++) ac2[i][j][q] = 0.f;

    #pragma unroll
    for (int ks8 = 0; ks8 < 8; ks8++) {
        const int ch = ks8 >> 2, ks = ks8 & 3;
        const uint32_t aHi = sb + ch * 8192, aLo = sb + 16384 + ch * 8192;
        const uint32_t wHi = wlr + ch * 16384, wLo = wlr + 32768 + ch * 16384;
        uint32_t ahi[2][4], alo[2][4];
        #pragma unroll
        for (int mi = 0; mi < 2; mi++) {
            LDSM_X4(ahi[mi], addrA(aHi, wm * 2 + mi, ks, lane));
            LDSM_X4(alo[mi], addrA(aLo, wm * 2 + mi, ks, lane));
        }
        uint32_t bh[2][4], bl[2][4];
        #pragma unroll
        for (int p = 0; p < 2; p++) {
            LDSM_X4(bh[p], addrB4(wHi, wn * 2 + p, ks, lane));
            LDSM_X4(bl[p], addrB4(wLo, wn * 2 + p, ks, lane));
        }
        #pragma unroll
        for (int ni = 0; ni < 4; ni++)
            #pragma unroll
            for (int mi = 0; mi < 2; mi++)
                MMA_BF16(ac2[mi][ni], ahi[mi], bh[ni >> 1][(ni & 1) * 2], bh[ni >> 1][(ni & 1) * 2 + 1]);
        #pragma unroll
        for (int ni = 0; ni < 4; ni++)
            #pragma unroll
            for (int mi = 0; mi < 2; mi++)
                MMA_BF16(ac2[mi][ni], ahi[mi], bl[ni >> 1][(ni & 1) * 2], bl[ni >> 1][(ni & 1) * 2 + 1]);
        #pragma unroll
        for (int ni = 0; ni < 4; ni++)
            #pragma unroll
            for (int mi = 0; mi < 2; mi++)
                MMA_BF16(ac2[mi][ni], alo[mi], bh[ni >> 1][(ni & 1) * 2], bh[ni >> 1][(ni & 1) * 2 + 1]);
    }
    #pragma unroll
    for (int ni = 0; ni < 4; ni++) {
        int cc = wn * 32 + ni * 8 + (lane & 3) * 2;
        float b0 = bL[cc], b1 = bL[cc + 1];
        #pragma unroll
        for (int mi = 0; mi < 2; mi++) {
            int r0 = row0 + wm * 32 + mi * 16 + (lane >> 2);
            #pragma unroll
            for (int half = 0; half < 2; half++) {
                int r = r0 + half * 8;
                if (r < NN) {
                    *(uint32_t*)&d_hRb[(size_t)r * HID + cc] =
                        packbf2(__float2bfloat16(ac2[mi][ni][half * 2 + 0] + b0),
                                __float2bfloat16(ac2[mi][ni][half * 2 + 1] + b1));
                }
            }
        }
    }
}

// ================= K3: bucket edges by dst =================
__global__ void edge_bucket_kernel(const int* __restrict__ ei) {
    int i = blockIdx.x * blockDim.x + threadIdx.x;
    if (i >= NEDGE) return;
    int src = ei[i];
    int dst = ei[NEDGE + i];
    if ((unsigned)src >= NN || (unsigned)dst >= NN) return;
    int pos = atomicAdd(&d_cnt[dst], 1);
    if (pos < CAP) d_slot[(size_t)dst * CAP + pos] = src;
}

// ================= K4: gather + combine + LN + relu + pool (MLP-8) =================
__global__ __launch_bounds__(256)
void gather_ln_pool_kernel(const float* __restrict__ lng,
                           const float* __restrict__ lnb)
{
    const int lane   = threadIdx.x & 31;
    const int warp   = threadIdx.x >> 5;
    const int nwarps = blockDim.x >> 5;

    const float4  g4  = ((const float4*)lng)[lane];
    const float4  b4  = ((const float4*)lnb)[lane];

    float4 pacc = make_float4(0.f, 0.f, 0.f, 0.f);

    for (int node = blockIdx.x * nwarps + warp; node < NN;
         node += gridDim.x * nwarps)
    {
        int deg = d_cnt[node];
        int dn  = min(deg, CAP);

        int sl[4];
        #pragma unroll
        for (int q = 0; q < 4; q++) {
            int idx = q * 32 + lane;
            sl[q] = (idx < dn) ? d_slot[(size_t)node * CAP + idx] : 0;
        }

        float4 a0 = make_float4(0.f, 0.f, 0.f, 0.f);
        float4 a1 = make_float4(0.f, 0.f, 0.f, 0.f);
        float4 a2 = make_float4(0.f, 0.f, 0.f, 0.f);
        float4 a3 = make_float4(0.f, 0.f, 0.f, 0.f);

        #pragma unroll
        for (int q = 0; q < 4; q++) {
            int base = q * 32;
            if (base >= dn) break;
            int cnt = min(32, dn - base);
            int my  = sl[q];
            int j = 0;
            #pragma unroll 1
            for (; j + 8 <= cnt; j += 8) {
                int s0 = __shfl_sync(0xffffffffu, my, j + 0);
                int s1 = __shfl_sync(0xffffffffu, my, j + 1);
                int s2 = __shfl_sync(0xffffffffu, my, j + 2);
                int s3 = __shfl_sync(0xffffffffu, my, j + 3);
                int s4 = __shfl_sync(0xffffffffu, my, j + 4);
                int s5 = __shfl_sync(0xffffffffu, my, j + 5);
                int s6 = __shfl_sync(0xffffffffu, my, j + 6);
                int s7 = __shfl_sync(0xffffffffu, my, j + 7);
                uint2 p0 = *(const uint2*)&d_hLb[(size_t)s0 * HID + lane * 4];
                uint2 p1 = *(const uint2*)&d_hLb[(size_t)s1 * HID + lane * 4];
                uint2 p2 = *(const uint2*)&d_hLb[(size_t)s2 * HID + lane * 4];
                uint2 p3 = *(const uint2*)&d_hLb[(size_t)s3 * HID + lane * 4];
                uint2 p4 = *(const uint2*)&d_hLb[(size_t)s4 * HID + lane * 4];
                uint2 p5 = *(const uint2*)&d_hLb[(size_t)s5 * HID + lane * 4];
                uint2 p6 = *(const uint2*)&d_hLb[(size_t)s6 * HID + lane * 4];
                uint2 p7 = *(const uint2*)&d_hLb[(size_t)s7 * HID + lane * 4];
                float2 f;
                f = __bfloat1622float2(*(__nv_bfloat162*)&p0.x); a0.x += f.x; a0.y += f.y;
                f = __bfloat1622float2(*(__nv_bfloat162*)&p0.y); a0.z += f.x; a0.w += f.y;
                f = __bfloat1622float2(*(__nv_bfloat162*)&p1.x); a1.x += f.x; a1.y += f.y;
                f = __bfloat1622float2(*(__nv_bfloat162*)&p1.y); a1.z += f.x; a1.w += f.y;
                f = __bfloat1622float2(*(__nv_bfloat162*)&p2.x); a2.x += f.x; a2.y += f.y;
                f = __bfloat1622float2(*(__nv_bfloat162*)&p2.y); a2.z += f.x; a2.w += f.y;
                f = __bfloat1622float2(*(__nv_bfloat162*)&p3.x); a3.x += f.x; a3.y += f.y;
                f = __bfloat1622float2(*(__nv_bfloat162*)&p3.y); a3.z += f.x; a3.w += f.y;
                f = __bfloat1622float2(*(__nv_bfloat162*)&p4.x); a0.x += f.x; a0.y += f.y;
                f = __bfloat1622float2(*(__nv_bfloat162*)&p4.y); a0.z += f.x; a0.w += f.y;
                f = __bfloat1622float2(*(__nv_bfloat162*)&p5.x); a1.x += f.x; a1.y += f.y;
                f = __bfloat1622float2(*(__nv_bfloat162*)&p5.y); a1.z += f.x; a1.w += f.y;
                f = __bfloat1622float2(*(__nv_bfloat162*)&p6.x); a2.x += f.x; a2.y += f.y;
                f = __bfloat1622float2(*(__nv_bfloat162*)&p6.y); a2.z += f.x; a2.w += f.y;
                f = __bfloat1622float2(*(__nv_bfloat162*)&p7.x); a3.x += f.x; a3.y += f.y;
                f = __bfloat1622float2(*(__nv_bfloat162*)&p7.y); a3.z += f.x; a3.w += f.y;
            }
            for (; j < cnt; j++) {
                int s = __shfl_sync(0xffffffffu, my, j);
                uint2 p = *(const uint2*)&d_hLb[(size_t)s * HID + lane * 4];
                float2 f;
                f = __bfloat1622float2(*(__nv_bfloat162*)&p.x); a0.x += f.x; a0.y += f.y;
                f = __bfloat1622float2(*(__nv_bfloat162*)&p.y); a0.z += f.x; a0.w += f.y;
            }
        }
        float4 acc;
        acc.x = (a0.x + a1.x) + (a2.x + a3.x);
        acc.y = (a0.y + a1.y) + (a2.y + a3.y);
        acc.z = (a0.z + a1.z) + (a2.z + a3.z);
        acc.w = (a0.w + a1.w) + (a2.w + a3.w);

        float inv = 1.f / fmaxf((float)deg, 1.f);
        uint2 pr = *(const uint2*)&d_hRb[(size_t)node * HID + lane * 4];
        float2 h0 = __bfloat1622float2(*(__nv_bfloat162*)&pr.x);
        float2 h1 = __bfloat1622float2(*(__nv_bfloat162*)&pr.y);
        float4 y;
        y.x = fmaf(acc.x, inv, h0.x);
        y.y = fmaf(acc.y, inv, h0.y);
        y.z = fmaf(acc.z, inv, h1.x);
        y.w = fmaf(acc.w, inv, h1.y);

        float s1 = y.x + y.y + y.z + y.w;
        float s2 = y.x * y.x + y.y * y.y + y.z * y.z + y.w * y.w;
        #pragma unroll
        for (int o = 16; o > 0; o >>= 1) {
            s1 += __shfl_xor_sync(0xffffffffu, s1, o);
            s2 += __shfl_xor_sync(0xffffffffu, s2, o);
        }
        float mu   = s1 * (1.f / 128.f);
        float var  = s2 * (1.f / 128.f) - mu * mu;
        float rstd = rsqrtf(var + 1e-5f);

        pacc.x += fmaxf((y.x - mu) * rstd * g4.x + b4.x, 0.f);
        pacc.y += fmaxf((y.y - mu) * rstd * g4.y + b4.y, 0.f);
        pacc.z += fmaxf((y.z - mu) * rstd * g4.z + b4.z, 0.f);
        pacc.w += fmaxf((y.w - mu) * rstd * g4.w + b4.w, 0.f);
    }

    __shared__ float sp[8][128];
    ((float4*)sp[warp])[lane] = pacc;
    __syncthreads();
    int t = threadIdx.x;
    if (t < HID) {
        float s = 0.f;
        #pragma unroll
        for (int w = 0; w < 8; w++) s += sp[w][t];
        atomicAdd(&d_pool[t], s);
    }
}

// ================= K5: final linear =================
__global__ void final_kernel(const float* __restrict__ ow,
                             const float* __restrict__ ob,
                             float* __restrict__ out)
{
    __shared__ float g[128];
    int t = threadIdx.x;
    g[t] = d_pool[t] * (1.f / (float)NN);
    __syncthreads();
    float s = ob[t];
    #pragma unroll 8
    for (int f = 0; f < 128; f++)
        s = fmaf(g[f], ow[(size_t)t * 128 + f], s);
    out[t] = s;
}

// ================= launch =================
extern "C" void kernel_launch(void* const* d_in, const int* in_sizes, int n_in,
                              void* d_out, int out_size)
{
    const float* x       = (const float*)d_in[0];
    const int*   ei      = (const int*)d_in[1];
    const float* proj_w  = (const float*)d_in[2];
    const float* proj_b  = (const float*)d_in[3];
    const float* lin_l_w = (const float*)d_in[4];
    const float* lin_l_b = (const float*)d_in[5];
    const float* lin_r_w = (const float*)d_in[6];
    const float* ln_g    = (const float*)d_in[7];
    const float* ln_b    = (const float*)d_in[8];
    const float* out_w   = (const float*)d_in[9];
    const float* out_b   = (const float*)d_in[10];
    float* out = (float*)d_out;

    static bool init_done = false;
    static cudaStream_t s2;
    static cudaEvent_t evA, evB;
    if (!init_done) {
        cudaFuncSetAttribute(fused_mma_kernel, cudaFuncAttributeMaxDynamicSharedMemorySize, KF_SMEM);
        cudaStreamCreateWithFlags(&s2, cudaStreamNonBlocking);
        cudaEventCreateWithFlags(&evA, cudaEventDisableTiming);
        cudaEventCreateWithFlags(&evB, cudaEventDisableTiming);
        init_done = true;
    }

    // fork: branch B = zero -> bucket
    cudaEventRecord(evA, 0);
    cudaStreamWaitEvent(s2, evA, 0);
    zero_kernel<<<(NN + 255) / 256, 256, 0, s2>>>();
    edge_bucket_kernel<<<(NEDGE + 255) / 256, 256, 0, s2>>>(ei);
    cudaEventRecord(evB, s2);

    // branch A: presplit -> fused
    presplit_kernel<<<160, 256>>>(proj_w, lin_l_w, lin_r_w);
    fused_mma_kernel<<<NBLK64, 256, KF_SMEM>>>(x, proj_b, lin_l_b);

    // join, then gather -> final
    cudaStreamWaitEvent(0, evB, 0);
    gather_ln_pool_kernel<<<1184, 256>>>(ln_g, ln_b);
    final_kernel<<<1, 128>>>(out_w, out_b, out);
}

// round 14
// speedup vs baseline: 1.0238x; 1.0145x over previous
#include <cuda_runtime.h>
#include <cuda_bf16.h>
#include <stdint.h>

#define NN    50000
#define NEDGE 1600000
#define NDIM  1024
#define HID   128
#define CAP   128
#define NBLK64 782   // ceil(NN/64)

// ================= scratch =================
__device__ uint8_t d_pwT[16][2][16384];          // proj_w  [ch][hl][tile]
__device__ uint8_t d_wT [2][2][2][16384];        // [w L/R][hl][ch][tile]
__device__ __nv_bfloat16 d_hLb[(size_t)NN * HID];
__device__ __nv_bfloat16 d_hRb[(size_t)NN * HID];
__device__ int           d_cnt[NN];
__device__ int           d_slot[(size_t)NN * CAP];
__device__ float         d_pool[HID];

// ================= helpers =================
__device__ __forceinline__ uint32_t smem_u32(const void* p) {
    uint32_t a;
    asm("{ .reg .u64 t; cvta.to.shared.u64 t, %1; cvt.u32.u64 %0, t; }" : "=r"(a) : "l"(p));
    return a;
}
#define SWZ128(o) ((o) ^ (((o) >> 3) & 0x70))

__device__ __forceinline__ uint32_t packbf2(__nv_bfloat16 a, __nv_bfloat16 b) {
    return (uint32_t)__bfloat16_as_ushort(a) | ((uint32_t)__bfloat16_as_ushort(b) << 16);
}
__device__ __forceinline__ void split4(float4 v, uint2& hi, uint2& lo) {
    __nv_bfloat16 hx = __float2bfloat16(v.x), hy = __float2bfloat16(v.y);
    __nv_bfloat16 hz = __float2bfloat16(v.z), hw = __float2bfloat16(v.w);
    __nv_bfloat16 lx = __float2bfloat16(v.x - __bfloat162float(hx));
    __nv_bfloat16 ly = __float2bfloat16(v.y - __bfloat162float(hy));
    __nv_bfloat16 lz = __float2bfloat16(v.z - __bfloat162float(hz));
    __nv_bfloat16 lw = __float2bfloat16(v.w - __bfloat162float(hw));
    hi.x = packbf2(hx, hy); hi.y = packbf2(hz, hw);
    lo.x = packbf2(lx, ly); lo.y = packbf2(lz, lw);
}
__device__ __forceinline__ uint2 cvt4hi(float4 v) {
    uint2 hi;
    hi.x = packbf2(__float2bfloat16(v.x), __float2bfloat16(v.y));
    hi.y = packbf2(__float2bfloat16(v.z), __float2bfloat16(v.w));
    return hi;
}

#define LDSM_X4(r, a) \
    asm volatile("ldmatrix.sync.aligned.m8n8.x4.shared.b16 {%0,%1,%2,%3}, [%4];" \
        : "=r"((r)[0]), "=r"((r)[1]), "=r"((r)[2]), "=r"((r)[3]) : "r"(a))
#define MMA_BF16(d, a, b0, b1) \
    asm volatile("mma.sync.aligned.m16n8k16.row.col.f32.bf16.bf16.f32 " \
        "{%0,%1,%2,%3}, {%4,%5,%6,%7}, {%8,%9}, {%0,%1,%2,%3};" \
        : "+f"((d)[0]), "+f"((d)[1]), "+f"((d)[2]), "+f"((d)[3]) \
        : "r"((a)[0]), "r"((a)[1]), "r"((a)[2]), "r"((a)[3]), "r"(b0), "r"(b1))

#define CP_A16(dst, src) \
    asm volatile("cp.async.cg.shared.global [%0], [%1], 16;" :: "r"(dst), "l"(src))
#define CP_COMMIT() asm volatile("cp.async.commit_group;")
#define CP_WAIT0()  asm volatile("cp.async.wait_group 0;" ::: "memory")

__device__ __forceinline__ uint32_t addrA(uint32_t base, int MI, int ks, int lane) {
    int row  = MI * 16 + (lane & 15);
    int kb   = ks * 32 + ((lane >> 4) << 4);
    return base + SWZ128((uint32_t)(row * 128 + kb));
}
// B x4: fragments for TWO adjacent n-tiles (pair p -> ni = 2p, 2p+1)
__device__ __forceinline__ uint32_t addrB4(uint32_t base, int p, int ks, int lane) {
    int ni  = p * 2 + ((lane >> 4) & 1);
    int row = ni * 8 + (lane & 7);
    int kb  = ks * 32 + (((lane >> 3) & 1) << 4);
    return base + SWZ128((uint32_t)(row * 128 + kb));
}

// ================= K0 =================
__global__ void zero_kernel() {
    int i = blockIdx.x * blockDim.x + threadIdx.x;
    if (i < NN)  d_cnt[i] = 0;
    if (i < HID) d_pool[i] = 0.f;
}

// ================= Kp: pre-split weights =================
__global__ void presplit_kernel(const float* __restrict__ pw,
                                const float* __restrict__ wl,
                                const float* __restrict__ wr)
{
    int i = blockIdx.x * blockDim.x + threadIdx.x;
    if (i < 32768) {
        int n  = i >> 8;
        int k4 = (i & 255) << 2;
        int ch = k4 >> 6, kk = k4 & 63;
        float4 v = ((const float4*)pw)[i];
        uint2 hi, lo; split4(v, hi, lo);
        uint32_t sw = SWZ128((uint32_t)(n * 128 + kk * 2));
        *(uint2*)&d_pwT[ch][0][sw] = hi;
        *(uint2*)&d_pwT[ch][1][sw] = lo;
    } else if (i < 40960) {
        int j = i - 32768;
        int w = j >= 4096;
        if (w) j -= 4096;
        const float* W = w ? wr : wl;
        int n  = j >> 5;
        int k4 = (j & 31) << 2;
        int ch = k4 >> 6, kk = k4 & 63;
        float4 v = ((const float4*)W)[j];
        uint2 hi, lo; split4(v, hi, lo);
        uint32_t sw = SWZ128((uint32_t)(n * 128 + kk * 2));
        *(uint2*)&d_wT[w][0][ch][sw] = hi;
        *(uint2*)&d_wT[w][1][ch][sw] = lo;
    }
}

// ================= KF: fused, M=64 tiles, 2 CTAs/SM, 1 barrier/chunk =================
// smem (96KB): A stage s @ s*8192; Wproj stage s @ 16384 + s*32768
//   post-mainloop: h hi ch @ ch*8192; h lo ch @ 16384 + ch*8192; WL/WR @ 32768
#define KF_SMEM 98304

__global__ __launch_bounds__(256, 2)
void fused_mma_kernel(const float* __restrict__ X, const float* __restrict__ bias,
                      const float* __restrict__ bL)
{
    extern __shared__ char smem[];
    const uint32_t sb = smem_u32(smem);
    const int tid  = threadIdx.x;
    const int lane = tid & 31;
    const int wid  = tid >> 5;
    const int wm   = wid & 1;
    const int wn   = wid >> 1;
    const int row0 = blockIdx.x * 64;

    float acc[2][4][4];
    #pragma unroll
    for (int i = 0; i < 2; i++)
        #pragma unroll
        for (int j = 0; j < 4; j++)
            #pragma unroll
            for (int q = 0; q < 4; q++) acc[i][j][q] = 0.f;

    // ---- prologue: x(0) -> regs -> A[0]; cp.async W0 -> stage 0
    float4 xv[4];
    #pragma unroll
    for (int it = 0; it < 4; it++) {
        int e = tid + it * 256;
        int r = e >> 4, c4 = (e & 15) << 2;
        int gm = row0 + r;
        xv[it] = (gm < NN) ? *(const float4*)&X[(size_t)gm * NDIM + c4]
                           : make_float4(0.f, 0.f, 0.f, 0.f);
    }
    {
        uint32_t wst = sb + 16384;
        const uint8_t* src = &d_pwT[0][0][0];
        #pragma unroll
        for (int q = 0; q < 8; q++)
            CP_A16(wst + tid * 16 + q * 4096, src + tid * 16 + q * 4096);
        CP_COMMIT();
    }
    #pragma unroll
    for (int it = 0; it < 4; it++) {
        int e = tid + it * 256;
        int r = e >> 4, c4 = (e & 15) << 2;
        *(uint2*)(smem + SWZ128((uint32_t)(r * 128 + c4 * 2))) = cvt4hi(xv[it]);
    }

    // ---- mainloop: ONE barrier per chunk.
    // Top barrier of iter c separates iter c-1's reads of stage s^1 (A and W)
    // from iter c's writes to them (split-store, cp.async) — both issued after it.
    #pragma unroll 1
    for (int c = 0; c < 16; c++) {
        const int s = c & 1;
        CP_WAIT0();          // own W(c) cp.asyncs complete
        __syncthreads();     // everyone's W(c) + A[s] (from iter c-1) visible

        if (c < 15) {
            // prefetch W(c+1) -> stage s^1 (safe: c-1's readers of s^1 are past barrier)
            uint32_t wst = sb + 16384 + (s ^ 1) * 32768;
            const uint8_t* src = &d_pwT[c + 1][0][0];
            #pragma unroll
            for (int q = 0; q < 8; q++)
                CP_A16(wst + tid * 16 + q * 4096, src + tid * 16 + q * 4096);
            CP_COMMIT();
            // prefetch x(c+1) -> regs (covered by MMA phase)
            const int kc = (c + 1) * 64;
            #pragma unroll
            for (int it = 0; it < 4; it++) {
                int e = tid + it * 256;
                int r = e >> 4, c4 = (e & 15) << 2;
                int gm = row0 + r;
                xv[it] = (gm < NN) ? *(const float4*)&X[(size_t)gm * NDIM + kc + c4]
                                   : make_float4(0.f, 0.f, 0.f, 0.f);
            }
        }

        const uint32_t aHi = sb + s * 8192;
        const uint32_t bHi = sb + 16384 + s * 32768, bLo = bHi + 16384;
        #pragma unroll
        for (int ks = 0; ks < 4; ks++) {
            uint32_t ahi[2][4];
            #pragma unroll
            for (int mi = 0; mi < 2; mi++)
                LDSM_X4(ahi[mi], addrA(aHi, wm * 2 + mi, ks, lane));
            uint32_t bh[2][4], bl[2][4];
            #pragma unroll
            for (int p = 0; p < 2; p++) {
                LDSM_X4(bh[p], addrB4(bHi, wn * 2 + p, ks, lane));
                LDSM_X4(bl[p], addrB4(bLo, wn * 2 + p, ks, lane));
            }
            #pragma unroll
            for (int ni = 0; ni < 4; ni++)
                #pragma unroll
                for (int mi = 0; mi < 2; mi++)
                    MMA_BF16(acc[mi][ni], ahi[mi], bh[ni >> 1][(ni & 1) * 2], bh[ni >> 1][(ni & 1) * 2 + 1]);
            #pragma unroll
            for (int ni = 0; ni < 4; ni++)
                #pragma unroll
                for (int mi = 0; mi < 2; mi++)
                    MMA_BF16(acc[mi][ni], ahi[mi], bl[ni >> 1][(ni & 1) * 2], bl[ni >> 1][(ni & 1) * 2 + 1]);
        }

        if (c < 15) {
            // split-store x(c+1) -> A[s^1] (safe: c-1's readers of s^1 are past barrier;
            // c+1's readers wait at the next top barrier)
            char* base = smem + (s ^ 1) * 8192;
            #pragma unroll
            for (int it = 0; it < 4; it++) {
                int e = tid + it * 256;
                int r = e >> 4, c4 = (e & 15) << 2;
                *(uint2*)(base + SWZ128((uint32_t)(r * 128 + c4 * 2))) = cvt4hi(xv[it]);
            }
        }
    }
    __syncthreads();   // all mainloop smem reads closed before h/WL overwrite

    // ---- issue WL cp.async (overlaps h-epilogue ALU)
    {
        const uint8_t* src = &d_wT[0][0][0][0];
        #pragma unroll
        for (int q = 0; q < 16; q++)
            CP_A16(sb + 32768 + tid * 16 + q * 4096, src + tid * 16 + q * 4096);
        CP_COMMIT();
    }

    // ---- h epilogue: bias+relu+split
    #pragma unroll
    for (int ni = 0; ni < 4; ni++) {
        int cc = wn * 32 + ni * 8 + (lane & 3) * 2;
        int ch = cc >> 6, kk = cc & 63;
        float b0 = bias[cc], b1 = bias[cc + 1];
        #pragma unroll
        for (int mi = 0; mi < 2; mi++) {
            int rl0 = wm * 32 + mi * 16 + (lane >> 2);
            #pragma unroll
            for (int half = 0; half < 2; half++) {
                int rl = rl0 + half * 8;
                float v0 = fmaxf(acc[mi][ni][half * 2 + 0] + b0, 0.f);
                float v1 = fmaxf(acc[mi][ni][half * 2 + 1] + b1, 0.f);
                __nv_bfloat16 h0 = __float2bfloat16(v0), h1 = __float2bfloat16(v1);
                __nv_bfloat16 l0 = __float2bfloat16(v0 - __bfloat162float(h0));
                __nv_bfloat16 l1 = __float2bfloat16(v1 - __bfloat162float(h1));
                uint32_t sw = SWZ128((uint32_t)(rl * 128 + kk * 2));
                *(uint32_t*)(smem + ch * 8192 + sw)         = packbf2(h0, h1);
                *(uint32_t*)(smem + 16384 + ch * 8192 + sw) = packbf2(l0, l1);
            }
        }
    }
    CP_WAIT0();
    __syncthreads();

    // ---- pass 0: hL = h @ WL^T (bf16 out), 3-term
    const uint32_t wlr = sb + 32768;
    float ac2[2][4][4];
    #pragma unroll
    for (int i = 0; i < 2; i++)
        #pragma unroll
        for (int j = 0; j < 4; j++)
            #pragma unroll
            for (int q = 0; q < 4; q++) ac2[i][j][q] = 0.f;

    #pragma unroll
    for (int ks8 = 0; ks8 < 8; ks8++) {
        const int ch = ks8 >> 2, ks = ks8 & 3;
        const uint32_t aHi = sb + ch * 8192, aLo = sb + 16384 + ch * 8192;
        const uint32_t wHi = wlr + ch * 16384, wLo = wlr + 32768 + ch * 16384;
        uint32_t ahi[2][4], alo[2][4];
        #pragma unroll
        for (int mi = 0; mi < 2; mi++) {
            LDSM_X4(ahi[mi], addrA(aHi, wm * 2 + mi, ks, lane));
            LDSM_X4(alo[mi], addrA(aLo, wm * 2 + mi, ks, lane));
        }
        uint32_t bh[2][4], bl[2][4];
        #pragma unroll
        for (int p = 0; p < 2; p++) {
            LDSM_X4(bh[p], addrB4(wHi, wn * 2 + p, ks, lane));
            LDSM_X4(bl[p], addrB4(wLo, wn * 2 + p, ks, lane));
        }
        #pragma unroll
        for (int ni = 0; ni < 4; ni++)
            #pragma unroll
            for (int mi = 0; mi < 2; mi++)
                MMA_BF16(ac2[mi][ni], ahi[mi], bh[ni >> 1][(ni & 1) * 2], bh[ni >> 1][(ni & 1) * 2 + 1]);
        #pragma unroll
        for (int ni = 0; ni < 4; ni++)
            #pragma unroll
            for (int mi = 0; mi < 2; mi++)
                MMA_BF16(ac2[mi][ni], ahi[mi], bl[ni >> 1][(ni & 1) * 2], bl[ni >> 1][(ni & 1) * 2 + 1]);
        #pragma unroll
        for (int ni = 0; ni < 4; ni++)
            #pragma unroll
            for (int mi = 0; mi < 2; mi++)
                MMA_BF16(ac2[mi][ni], alo[mi], bh[ni >> 1][(ni & 1) * 2], bh[ni >> 1][(ni & 1) * 2 + 1]);
    }
    __syncthreads();   // WL reads closed

    {
        const uint8_t* src = &d_wT[1][0][0][0];
        #pragma unroll
        for (int q = 0; q < 16; q++)
            CP_A16(wlr + tid * 16 + q * 4096, src + tid * 16 + q * 4096);
        CP_COMMIT();
    }
    #pragma unroll
    for (int ni = 0; ni < 4; ni++) {
        int cc = wn * 32 + ni * 8 + (lane & 3) * 2;
        #pragma unroll
        for (int mi = 0; mi < 2; mi++) {
            int r0 = row0 + wm * 32 + mi * 16 + (lane >> 2);
            #pragma unroll
            for (int half = 0; half < 2; half++) {
                int r = r0 + half * 8;
                if (r < NN) {
                    *(uint32_t*)&d_hLb[(size_t)r * HID + cc] =
                        packbf2(__float2bfloat16(ac2[mi][ni][half * 2 + 0]),
                                __float2bfloat16(ac2[mi][ni][half * 2 + 1]));
                }
            }
        }
    }
    CP_WAIT0();
    __syncthreads();

    // ---- pass 1: hR = h @ WR^T + bL (bf16 out), 3-term
    #pragma unroll
    for (int i = 0; i < 2; i++)
        #pragma unroll
        for (int j = 0; j < 4; j++)
            #pragma unroll
            for (int q = 0; q < 4; q++) ac2[i][j][q] = 0.f;

    #pragma unroll
    for (int ks8 = 0; ks8 < 8; ks8++) {
        const int ch = ks8 >> 2, ks = ks8 & 3;
        const uint32_t aHi = sb + ch * 8192, aLo = sb + 16384 + ch * 8192;
        const uint32_t wHi = wlr + ch * 16384, wLo = wlr + 32768 + ch * 16384;
        uint32_t ahi[2][4], alo[2][4];
        #pragma unroll
        for (int mi = 0; mi < 2; mi++) {
            LDSM_X4(ahi[mi], addrA(aHi, wm * 2 + mi, ks, lane));
            LDSM_X4(alo[mi], addrA(aLo, wm * 2 + mi, ks, lane));
        }
        uint32_t bh[2][4], bl[2][4];
        #pragma unroll
        for (int p = 0; p < 2; p++) {
            LDSM_X4(bh[p], addrB4(wHi, wn * 2 + p, ks, lane));
            LDSM_X4(bl[p], addrB4(wLo, wn * 2 + p, ks, lane));
        }
        #pragma unroll
        for (int ni = 0; ni < 4; ni++)
            #pragma unroll
            for (int mi = 0; mi < 2; mi++)
                MMA_BF16(ac2[mi][ni], ahi[mi], bh[ni >> 1][(ni & 1) * 2], bh[ni >> 1][(ni & 1) * 2 + 1]);
        #pragma unroll
        for (int ni = 0; ni < 4; ni++)
            #pragma unroll
            for (int mi = 0; mi < 2; mi++)
                MMA_BF16(ac2[mi][ni], ahi[mi], bl[ni >> 1][(ni & 1) * 2], bl[ni >> 1][(ni & 1) * 2 + 1]);
        #pragma unroll
        for (int ni = 0; ni < 4; ni++)
            #pragma unroll
            for (int mi = 0; mi < 2; mi++)
                MMA_BF16(ac2[mi][ni], alo[mi], bh[ni >> 1][(ni & 1) * 2], bh[ni >> 1][(ni & 1) * 2 + 1]);
    }
    #pragma unroll
    for (int ni = 0; ni < 4; ni++) {
        int cc = wn * 32 + ni * 8 + (lane & 3) * 2;
        float b0 = bL[cc], b1 = bL[cc + 1];
        #pragma unroll
        for (int mi = 0; mi < 2; mi++) {
            int r0 = row0 + wm * 32 + mi * 16 + (lane >> 2);
            #pragma unroll
            for (int half = 0; half < 2; half++) {
                int r = r0 + half * 8;
                if (r < NN) {
                    *(uint32_t*)&d_hRb[(size_t)r * HID + cc] =
                        packbf2(__float2bfloat16(ac2[mi][ni][half * 2 + 0] + b0),
                                __float2bfloat16(ac2[mi][ni][half * 2 + 1] + b1));
                }
            }
        }
    }
}

// ================= K3: bucket edges by dst =================
__global__ void edge_bucket_kernel(const int* __restrict__ ei) {
    int i = blockIdx.x * blockDim.x + threadIdx.x;
    if (i >= NEDGE) return;
    int src = ei[i];
    int dst = ei[NEDGE + i];
    if ((unsigned)src >= NN || (unsigned)dst >= NN) return;
    int pos = atomicAdd(&d_cnt[dst], 1);
    if (pos < CAP) d_slot[(size_t)dst * CAP + pos] = src;
}

// ================= K4: gather + combine + LN + relu + pool (MLP-8) =================
__global__ __launch_bounds__(256)
void gather_ln_pool_kernel(const float* __restrict__ lng,
                           const float* __restrict__ lnb)
{
    const int lane   = threadIdx.x & 31;
    const int warp   = threadIdx.x >> 5;
    const int nwarps = blockDim.x >> 5;

    const float4  g4  = ((const float4*)lng)[lane];
    const float4  b4  = ((const float4*)lnb)[lane];

    float4 pacc = make_float4(0.f, 0.f, 0.f, 0.f);

    for (int node = blockIdx.x * nwarps + warp; node < NN;
         node += gridDim.x * nwarps)
    {
        int deg = d_cnt[node];
        int dn  = min(deg, CAP);

        int sl[4];
        #pragma unroll
        for (int q = 0; q < 4; q++) {
            int idx = q * 32 + lane;
            sl[q] = (idx < dn) ? d_slot[(size_t)node * CAP + idx] : 0;
        }

        float4 a0 = make_float4(0.f, 0.f, 0.f, 0.f);
        float4 a1 = make_float4(0.f, 0.f, 0.f, 0.f);
        float4 a2 = make_float4(0.f, 0.f, 0.f, 0.f);
        float4 a3 = make_float4(0.f, 0.f, 0.f, 0.f);

        #pragma unroll
        for (int q = 0; q < 4; q++) {
            int base = q * 32;
            if (base >= dn) break;
            int cnt = min(32, dn - base);
            int my  = sl[q];
            int j = 0;
            #pragma unroll 1
            for (; j + 8 <= cnt; j += 8) {
                int s0 = __shfl_sync(0xffffffffu, my, j + 0);
                int s1 = __shfl_sync(0xffffffffu, my, j + 1);
                int s2 = __shfl_sync(0xffffffffu, my, j + 2);
                int s3 = __shfl_sync(0xffffffffu, my, j + 3);
                int s4 = __shfl_sync(0xffffffffu, my, j + 4);
                int s5 = __shfl_sync(0xffffffffu, my, j + 5);
                int s6 = __shfl_sync(0xffffffffu, my, j + 6);
                int s7 = __shfl_sync(0xffffffffu, my, j + 7);
                uint2 p0 = *(const uint2*)&d_hLb[(size_t)s0 * HID + lane * 4];
                uint2 p1 = *(const uint2*)&d_hLb[(size_t)s1 * HID + lane * 4];
                uint2 p2 = *(const uint2*)&d_hLb[(size_t)s2 * HID + lane * 4];
                uint2 p3 = *(const uint2*)&d_hLb[(size_t)s3 * HID + lane * 4];
                uint2 p4 = *(const uint2*)&d_hLb[(size_t)s4 * HID + lane * 4];
                uint2 p5 = *(const uint2*)&d_hLb[(size_t)s5 * HID + lane * 4];
                uint2 p6 = *(const uint2*)&d_hLb[(size_t)s6 * HID + lane * 4];
                uint2 p7 = *(const uint2*)&d_hLb[(size_t)s7 * HID + lane * 4];
                float2 f;
                f = __bfloat1622float2(*(__nv_bfloat162*)&p0.x); a0.x += f.x; a0.y += f.y;
                f = __bfloat1622float2(*(__nv_bfloat162*)&p0.y); a0.z += f.x; a0.w += f.y;
                f = __bfloat1622float2(*(__nv_bfloat162*)&p1.x); a1.x += f.x; a1.y += f.y;
                f = __bfloat1622float2(*(__nv_bfloat162*)&p1.y); a1.z += f.x; a1.w += f.y;
                f = __bfloat1622float2(*(__nv_bfloat162*)&p2.x); a2.x += f.x; a2.y += f.y;
                f = __bfloat1622float2(*(__nv_bfloat162*)&p2.y); a2.z += f.x; a2.w += f.y;
                f = __bfloat1622float2(*(__nv_bfloat162*)&p3.x); a3.x += f.x; a3.y += f.y;
                f = __bfloat1622float2(*(__nv_bfloat162*)&p3.y); a3.z += f.x; a3.w += f.y;
                f = __bfloat1622float2(*(__nv_bfloat162*)&p4.x); a0.x += f.x; a0.y += f.y;
                f = __bfloat1622float2(*(__nv_bfloat162*)&p4.y); a0.z += f.x; a0.w += f.y;
                f = __bfloat1622float2(*(__nv_bfloat162*)&p5.x); a1.x += f.x; a1.y += f.y;
                f = __bfloat1622float2(*(__nv_bfloat162*)&p5.y); a1.z += f.x; a1.w += f.y;
                f = __bfloat1622float2(*(__nv_bfloat162*)&p6.x); a2.x += f.x; a2.y += f.y;
                f = __bfloat1622float2(*(__nv_bfloat162*)&p6.y); a2.z += f.x; a2.w += f.y;
                f = __bfloat1622float2(*(__nv_bfloat162*)&p7.x); a3.x += f.x; a3.y += f.y;
                f = __bfloat1622float2(*(__nv_bfloat162*)&p7.y); a3.z += f.x; a3.w += f.y;
            }
            for (; j < cnt; j++) {
                int s = __shfl_sync(0xffffffffu, my, j);
                uint2 p = *(const uint2*)&d_hLb[(size_t)s * HID + lane * 4];
                float2 f;
                f = __bfloat1622float2(*(__nv_bfloat162*)&p.x); a0.x += f.x; a0.y += f.y;
                f = __bfloat1622float2(*(__nv_bfloat162*)&p.y); a0.z += f.x; a0.w += f.y;
            }
        }
        float4 acc;
        acc.x = (a0.x + a1.x) + (a2.x + a3.x);
        acc.y = (a0.y + a1.y) + (a2.y + a3.y);
        acc.z = (a0.z + a1.z) + (a2.z + a3.z);
        acc.w = (a0.w + a1.w) + (a2.w + a3.w);

        float inv = 1.f / fmaxf((float)deg, 1.f);
        uint2 pr = *(const uint2*)&d_hRb[(size_t)node * HID + lane * 4];
        float2 h0 = __bfloat1622float2(*(__nv_bfloat162*)&pr.x);
        float2 h1 = __bfloat1622float2(*(__nv_bfloat162*)&pr.y);
        float4 y;
        y.x = fmaf(acc.x, inv, h0.x);
        y.y = fmaf(acc.y, inv, h0.y);
        y.z = fmaf(acc.z, inv, h1.x);
        y.w = fmaf(acc.w, inv, h1.y);

        float s1 = y.x + y.y + y.z + y.w;
        float s2 = y.x * y.x + y.y * y.y + y.z * y.z + y.w * y.w;
        #pragma unroll
        for (int o = 16; o > 0; o >>= 1) {
            s1 += __shfl_xor_sync(0xffffffffu, s1, o);
            s2 += __shfl_xor_sync(0xffffffffu, s2, o);
        }
        float mu   = s1 * (1.f / 128.f);
        float var  = s2 * (1.f / 128.f) - mu * mu;
        float rstd = rsqrtf(var + 1e-5f);

        pacc.x += fmaxf((y.x - mu) * rstd * g4.x + b4.x, 0.f);
        pacc.y += fmaxf((y.y - mu) * rstd * g4.y + b4.y, 0.f);
        pacc.z += fmaxf((y.z - mu) * rstd * g4.z + b4.z, 0.f);
        pacc.w += fmaxf((y.w - mu) * rstd * g4.w + b4.w, 0.f);
    }

    __shared__ float sp[8][128];
    ((float4*)sp[warp])[lane] = pacc;
    __syncthreads();
    int t = threadIdx.x;
    if (t < HID) {
        float s = 0.f;
        #pragma unroll
        for (int w = 0; w < 8; w++) s += sp[w][t];
        atomicAdd(&d_pool[t], s);
    }
}

// ================= K5: final linear =================
__global__ void final_kernel(const float* __restrict__ ow,
                             const float* __restrict__ ob,
                             float* __restrict__ out)
{
    __shared__ float g[128];
    int t = threadIdx.x;
    g[t] = d_pool[t] * (1.f / (float)NN);
    __syncthreads();
    float s = ob[t];
    #pragma unroll 8
    for (int f = 0; f < 128; f++)
        s = fmaf(g[f], ow[(size_t)t * 128 + f], s);
    out[t] = s;
}

// ================= launch =================
extern "C" void kernel_launch(void* const* d_in, const int* in_sizes, int n_in,
                              void* d_out, int out_size)
{
    const float* x       = (const float*)d_in[0];
    const int*   ei      = (const int*)d_in[1];
    const float* proj_w  = (const float*)d_in[2];
    const float* proj_b  = (const float*)d_in[3];
    const float* lin_l_w = (const float*)d_in[4];
    const float* lin_l_b = (const float*)d_in[5];
    const float* lin_r_w = (const float*)d_in[6];
    const float* ln_g    = (const float*)d_in[7];
    const float* ln_b    = (const float*)d_in[8];
    const float* out_w   = (const float*)d_in[9];
    const float* out_b   = (const float*)d_in[10];
    float* out = (float*)d_out;

    static bool init_done = false;
    static cudaStream_t s2;
    static cudaEvent_t evA, evB;
    if (!init_done) {
        cudaFuncSetAttribute(fused_mma_kernel, cudaFuncAttributeMaxDynamicSharedMemorySize, KF_SMEM);
        cudaStreamCreateWithFlags(&s2, cudaStreamNonBlocking);
        cudaEventCreateWithFlags(&evA, cudaEventDisableTiming);
        cudaEventCreateWithFlags(&evB, cudaEventDisableTiming);
        init_done = true;
    }

    // fork: branch B = zero -> bucket
    cudaEventRecord(evA, 0);
    cudaStreamWaitEvent(s2, evA, 0);
    zero_kernel<<<(NN + 255) / 256, 256, 0, s2>>>();
    edge_bucket_kernel<<<(NEDGE + 255) / 256, 256, 0, s2>>>(ei);
    cudaEventRecord(evB, s2);

    // branch A: presplit -> fused
    presplit_kernel<<<160, 256>>>(proj_w, lin_l_w, lin_r_w);
    fused_mma_kernel<<<NBLK64, 256, KF_SMEM>>>(x, proj_b, lin_l_b);

    // join, then gather -> final
    cudaStreamWaitEvent(0, evB, 0);
    gather_ln_pool_kernel<<<1184, 256>>>(ln_g, ln_b);
    final_kernel<<<1, 128>>>(out_w, out_b, out);
}